// round 1
// baseline (speedup 1.0000x reference)
#include <cuda_runtime.h>
#include <cstdint>

// CrossScan: x (B=16, C=96, H=128, W=128) fp32 ->
// out (B, 4, C, H*W):
//   s=0: row-major flatten (identity)
//   s=1: HW-transposed flatten
//   s=2: s=0 reversed
//   s=3: s=1 reversed

#define B_ 16
#define C_ 96
#define H_ 128
#define W_ 128
#define HW_ (H_ * W_)

// smem tile: 32 rows (h) x 128 cols (w), stride 132 floats.
// STS.128 phase: 16B-unit bank pattern 4(r+tx) mod 32 -> conflict-free.
// LDS.128 phase: 16B-unit bank pattern 4(tx+wq) mod 32 -> conflict-free.
#define TSTRIDE 132

__global__ __launch_bounds__(256) void cross_scan_kernel(
    const float* __restrict__ x, float* __restrict__ out)
{
    __shared__ float tile[32 * TSTRIDE];

    const int bc = blockIdx.y;          // 0 .. B*C-1
    const int b  = bc / C_;
    const int c  = bc - b * C_;
    const int h0 = blockIdx.x * 32;     // tile's first row

    const int tx = threadIdx.x;         // 0..31
    const int ty = threadIdx.y;         // 0..7

    const float* in = x + (size_t)bc * HW_;
    float* o0 = out + ((size_t)(b * 4 + 0) * C_ + c) * HW_;
    float* o1 = out + ((size_t)(b * 4 + 1) * C_ + c) * HW_;
    float* o2 = out + ((size_t)(b * 4 + 2) * C_ + c) * HW_;
    float* o3 = out + ((size_t)(b * 4 + 3) * C_ + c) * HW_;

    // ---- Phase 1: load tile, write y0 (identity) and y2 (reversed) ----
    const int wb = tx * 4;  // float4 column base
#pragma unroll
    for (int i = 0; i < 4; ++i) {
        const int r = ty + i * 8;       // row within tile
        const int h = h0 + r;
        const int j = h * W_ + wb;      // flat index of first element

        float4 v = *reinterpret_cast<const float4*>(in + j);

        // y0: identity, coalesced
        *reinterpret_cast<float4*>(o0 + j) = v;

        // y2: out2[HW-1-k] = x[k]. The 4 elems j..j+3 land at HW-4-j..HW-1-j,
        // reversed component order. Base HW-4-j is 16B aligned (all terms %4==0).
        float4 rv = make_float4(v.w, v.z, v.y, v.x);
        *reinterpret_cast<float4*>(o2 + (HW_ - 4 - j)) = rv;

        // stash into smem for the transpose phase
        *reinterpret_cast<float4*>(&tile[r * TSTRIDE + wb]) = v;
    }

    __syncthreads();

    // ---- Phase 2: transposed views y1, y3 ----
    // y1[w*H + h] = x[h][w]. This block covers h in [h0, h0+32), w in [0,128).
    // Thread (tx,ty): h = h0 + tx, w = 4*wq .. 4*wq+3 with wq = ty + 8*it.
#pragma unroll
    for (int it = 0; it < 4; ++it) {
        const int wq = ty + it * 8;     // 0..31, float4 group along w
        float4 v = *reinterpret_cast<const float4*>(&tile[tx * TSTRIDE + 4 * wq]);

        const int h = h0 + tx;
        const int w0base = 4 * wq;

        // per-k: addresses w*H + h -> 32 consecutive floats across the warp
        o1[(w0base + 0) * H_ + h] = v.x;
        o1[(w0base + 1) * H_ + h] = v.y;
        o1[(w0base + 2) * H_ + h] = v.z;
        o1[(w0base + 3) * H_ + h] = v.w;

        // y3: reversed transpose. Descending-contiguous across warp -> coalesced.
        o3[HW_ - 1 - ((w0base + 0) * H_ + h)] = v.x;
        o3[HW_ - 1 - ((w0base + 1) * H_ + h)] = v.y;
        o3[HW_ - 1 - ((w0base + 2) * H_ + h)] = v.z;
        o3[HW_ - 1 - ((w0base + 3) * H_ + h)] = v.w;
    }
}

extern "C" void kernel_launch(void* const* d_in, const int* in_sizes, int n_in,
                              void* d_out, int out_size)
{
    const float* x = (const float*)d_in[0];
    float* out = (float*)d_out;
    (void)in_sizes; (void)n_in; (void)out_size;

    dim3 block(32, 8);
    dim3 grid(H_ / 32, B_ * C_);
    cross_scan_kernel<<<grid, block>>>(x, out);
}